// round 1
// baseline (speedup 1.0000x reference)
#include <cuda_runtime.h>
#include <math.h>

#define BATCH 2048

// Scratch (alloc-free): bufA holds 16-ch activations (h1, then h3); bufB holds 8-ch (h2, then g)
__device__ float g_bufA[(size_t)BATCH * 16 * 1024];
__device__ float g_bufB[(size_t)BATCH * 8 * 1024];
__device__ float g_ang[BATCH * 4];
__device__ float g_q[BATCH * 4];

// ---------------------------------------------------------------------------
// Direct 3x3 SAME conv, NCHW, 32x32 images. One block = one image, 8 rows.
// ACT: 0 = relu, 1 = sigmoid
// ---------------------------------------------------------------------------
template <int CIN, int COUT, int ACT>
__global__ __launch_bounds__(256) void conv3x3_kernel(
    const float* __restrict__ in, const float* __restrict__ w,
    const float* __restrict__ bias, float* __restrict__ out)
{
    __shared__ float s_in[CIN * 10 * 34];   // 8 rows + halo, 32 cols + halo
    __shared__ float s_w[COUT * CIN * 9];
    __shared__ float s_b[COUT];

    const int b  = blockIdx.y;
    const int y0 = blockIdx.x * 8;
    const int tx = threadIdx.x & 31;
    const int ty = threadIdx.x >> 5;

    for (int i = threadIdx.x; i < COUT * CIN * 9; i += 256) s_w[i] = w[i];
    if (threadIdx.x < COUT) s_b[threadIdx.x] = bias[threadIdx.x];

    const float* inb = in + (size_t)b * CIN * 1024;
    for (int i = threadIdx.x; i < CIN * 340; i += 256) {
        int c   = i / 340;
        int rem = i - c * 340;
        int r   = rem / 34;
        int col = rem - r * 34;
        int gy = y0 + r - 1;
        int gx = col - 1;
        float v = 0.f;
        if ((unsigned)gy < 32u && (unsigned)gx < 32u)
            v = inb[c * 1024 + gy * 32 + gx];
        s_in[i] = v;
    }
    __syncthreads();

    float acc[COUT];
#pragma unroll
    for (int co = 0; co < COUT; co++) acc[co] = s_b[co];

#pragma unroll
    for (int ci = 0; ci < CIN; ci++) {
        float v[9];
#pragma unroll
        for (int dy = 0; dy < 3; dy++)
#pragma unroll
            for (int dx = 0; dx < 3; dx++)
                v[dy * 3 + dx] = s_in[ci * 340 + (ty + dy) * 34 + tx + dx];
#pragma unroll
        for (int co = 0; co < COUT; co++)
#pragma unroll
            for (int k = 0; k < 9; k++)
                acc[co] = fmaf(v[k], s_w[(co * CIN + ci) * 9 + k], acc[co]);
    }

    float* outp = out + (size_t)b * COUT * 1024 + (y0 + ty) * 32 + tx;
#pragma unroll
    for (int co = 0; co < COUT; co++) {
        float r = acc[co];
        if (ACT == 0) r = fmaxf(r, 0.f);
        if (ACT == 1) r = 1.f / (1.f + expf(-r));
        outp[co * 1024] = r;
    }
}

// ---------------------------------------------------------------------------
// fc: ang[b][j] = sum_k h[b][k] * fc_w[j][k] + fc_b[j]   (K=8192, J=4)
// One block per batch row.
// ---------------------------------------------------------------------------
__global__ __launch_bounds__(256) void fc_kernel(
    const float* __restrict__ h, const float* __restrict__ w,
    const float* __restrict__ bias, float* __restrict__ ang)
{
    __shared__ float red[4][256];
    const int bb = blockIdx.x;
    const float4* hr = (const float4*)(h + (size_t)bb * 8192);
    float acc[4] = {0.f, 0.f, 0.f, 0.f};
    for (int k = threadIdx.x; k < 2048; k += 256) {
        float4 hv = hr[k];
#pragma unroll
        for (int j = 0; j < 4; j++) {
            float4 wv = ((const float4*)(w + j * 8192))[k];
            acc[j] += hv.x * wv.x + hv.y * wv.y + hv.z * wv.z + hv.w * wv.w;
        }
    }
#pragma unroll
    for (int j = 0; j < 4; j++) red[j][threadIdx.x] = acc[j];
    __syncthreads();
    for (int s = 128; s > 0; s >>= 1) {
        if (threadIdx.x < s)
#pragma unroll
            for (int j = 0; j < 4; j++)
                red[j][threadIdx.x] += red[j][threadIdx.x + s];
        __syncthreads();
    }
    if (threadIdx.x < 4)
        ang[bb * 4 + threadIdx.x] = red[threadIdx.x][0] + bias[threadIdx.x];
}

// ---------------------------------------------------------------------------
// 4-qubit statevector sim, one thread per batch element; 16 complex amps in regs.
// Wire w maps to bit (3-w) of the flat amplitude index.
// ---------------------------------------------------------------------------
__device__ __forceinline__ float2 cmul(float2 a, float2 b) {
    return make_float2(a.x * b.x - a.y * b.y, a.x * b.y + a.y * b.x);
}

__global__ __launch_bounds__(256) void quantum_kernel(
    const float* __restrict__ ang, const float* __restrict__ qw,
    float* __restrict__ qout)
{
    const int b = blockIdx.x * 256 + threadIdx.x;
    if (b >= BATCH) return;

    float2 st[16];
#pragma unroll
    for (int i = 0; i < 16; i++) st[i] = make_float2(0.f, 0.f);
    st[0].x = 1.f;

    // AngleEmbedding: RX(angle[w]) on wire w
#pragma unroll
    for (int w = 0; w < 4; w++) {
        float half = ang[b * 4 + w] * 0.5f;
        float c, s;
        __sincosf(half, &s, &c);
        s = sinf(half); c = cosf(half);   // precise versions
        const int bit = 1 << (3 - w);
#pragma unroll
        for (int i = 0; i < 16; i++) {
            if (i & bit) continue;
            float2 a0 = st[i], a1 = st[i | bit];
            // a0' = c*a0 + (-i s)*a1 ; a1' = (-i s)*a0 + c*a1
            st[i]       = make_float2(c * a0.x + s * a1.y, c * a0.y - s * a1.x);
            st[i | bit] = make_float2(c * a1.x + s * a0.y, c * a1.y - s * a0.x);
        }
    }

    // StronglyEntanglingLayers
#pragma unroll
    for (int l = 0; l < 3; l++) {
#pragma unroll
        for (int w = 0; w < 4; w++) {
            float phi = qw[(l * 4 + w) * 3 + 0];
            float th  = qw[(l * 4 + w) * 3 + 1];
            float om  = qw[(l * 4 + w) * 3 + 2];
            float ct = cosf(th * 0.5f), stt = sinf(th * 0.5f);
            float a = (phi + om) * 0.5f, d = (phi - om) * 0.5f;
            float ca = cosf(a), sa = sinf(a), cd = cosf(d), sd = sinf(d);
            float2 U00 = make_float2(ct * ca, -ct * sa);    // e^{-ia} ct
            float2 U01 = make_float2(-stt * cd, -stt * sd); // -e^{ id} st
            float2 U10 = make_float2(stt * cd, -stt * sd);  //  e^{-id} st
            float2 U11 = make_float2(ct * ca, ct * sa);     //  e^{ ia} ct
            const int bit = 1 << (3 - w);
#pragma unroll
            for (int i = 0; i < 16; i++) {
                if (i & bit) continue;
                float2 a0 = st[i], a1 = st[i | bit];
                float2 n0 = cmul(U00, a0), n1 = cmul(U10, a0);
                float2 m0 = cmul(U01, a1), m1 = cmul(U11, a1);
                st[i]       = make_float2(n0.x + m0.x, n0.y + m0.y);
                st[i | bit] = make_float2(n1.x + m1.x, n1.y + m1.y);
            }
        }
        const int r = (l % 3) + 1;
#pragma unroll
        for (int w = 0; w < 4; w++) {
            const int cb = 1 << (3 - w);
            const int tb = 1 << (3 - ((w + r) & 3));
#pragma unroll
            for (int i = 0; i < 16; i++) {
                if ((i & cb) && !(i & tb)) {
                    float2 tmp = st[i];
                    st[i] = st[i | tb];
                    st[i | tb] = tmp;
                }
            }
        }
    }

    float p[16];
#pragma unroll
    for (int i = 0; i < 16; i++) p[i] = st[i].x * st[i].x + st[i].y * st[i].y;
#pragma unroll
    for (int w = 0; w < 4; w++) {
        const int bit = 1 << (3 - w);
        float ev = 0.f;
#pragma unroll
        for (int i = 0; i < 16; i++) ev += (i & bit) ? -p[i] : p[i];
        qout[b * 4 + w] = ev;
    }
}

// ---------------------------------------------------------------------------
// fc2: out[b][k] = sum_j q[b][j] * fc2_w[k][j] + fc2_b[k]   (fc2_w is (8192,4))
// ---------------------------------------------------------------------------
__global__ __launch_bounds__(256) void fc2_kernel(
    const float* __restrict__ q, const float* __restrict__ w,
    const float* __restrict__ bias, float* __restrict__ out)
{
    const int idx = blockIdx.x * 256 + threadIdx.x;
    const int b = idx >> 13;
    const int k = idx & 8191;
    float4 wv = ((const float4*)w)[k];
    float4 qv = ((const float4*)q)[b];
    out[idx] = fmaf(qv.x, wv.x, fmaf(qv.y, wv.y, fmaf(qv.z, wv.z, qv.w * wv.w))) + bias[k];
}

// ---------------------------------------------------------------------------

extern "C" void kernel_launch(void* const* d_in, const int* in_sizes, int n_in,
                              void* d_out, int out_size)
{
    const float* x   = (const float*)d_in[0];
    const float* c1w = (const float*)d_in[1];
    const float* c1b = (const float*)d_in[2];
    const float* c2w = (const float*)d_in[3];
    const float* c2b = (const float*)d_in[4];
    const float* fcw = (const float*)d_in[5];
    const float* fcb = (const float*)d_in[6];
    const float* qw  = (const float*)d_in[7];
    const float* f2w = (const float*)d_in[8];
    const float* f2b = (const float*)d_in[9];
    const float* d1w = (const float*)d_in[10];
    const float* d1b = (const float*)d_in[11];
    const float* d2w = (const float*)d_in[12];
    const float* d2b = (const float*)d_in[13];
    float* out = (float*)d_out;

    float *bufA, *bufB, *ang, *qv;
    cudaGetSymbolAddress((void**)&bufA, g_bufA);
    cudaGetSymbolAddress((void**)&bufB, g_bufB);
    cudaGetSymbolAddress((void**)&ang,  g_ang);
    cudaGetSymbolAddress((void**)&qv,   g_q);

    dim3 cg(4, BATCH);
    conv3x3_kernel<3, 16, 0><<<cg, 256>>>(x, c1w, c1b, bufA);
    conv3x3_kernel<16, 8, 0><<<cg, 256>>>(bufA, c2w, c2b, bufB);
    fc_kernel<<<BATCH, 256>>>(bufB, fcw, fcb, ang);
    quantum_kernel<<<BATCH / 256, 256>>>(ang, qw, qv);
    fc2_kernel<<<(BATCH * 8192) / 256, 256>>>(qv, f2w, f2b, bufB);
    conv3x3_kernel<8, 16, 0><<<cg, 256>>>(bufB, d1w, d1b, bufA);
    conv3x3_kernel<16, 3, 1><<<cg, 256>>>(bufA, d2w, d2b, out);
}

// round 2
// speedup vs baseline: 1.4284x; 1.4284x over previous
#include <cuda_runtime.h>
#include <math.h>

#define BATCH 2048

// Scratch (alloc-free device globals)
__device__ float g_h1[(size_t)BATCH * 16 * 1024];   // conv1 output
__device__ float g_part[BATCH * 4 * 4];             // per-(b,chunk) fc partials [b][chunk][j]
__device__ float g_q[BATCH * 4];                    // quantum expvals
__device__ float g_Y[5 * 16 * 1024];                // dconv1(W_j) j=0..3, + dconv1(fc2_b)+d1b

// ---------------------------------------------------------------------------
// conv1: 3 -> 16, relu. One block = one image x 8 rows.
// ---------------------------------------------------------------------------
__global__ __launch_bounds__(256) void conv1_kernel(
    const float* __restrict__ in, const float* __restrict__ w,
    const float* __restrict__ bias, float* __restrict__ out)
{
    __shared__ float s_in[3 * 10 * 34];
    __shared__ float s_w[16 * 3 * 9];
    __shared__ float s_b[16];

    const int b  = blockIdx.y;
    const int y0 = blockIdx.x * 8;
    const int tx = threadIdx.x & 31;
    const int ty = threadIdx.x >> 5;

    for (int i = threadIdx.x; i < 16 * 27; i += 256) s_w[i] = w[i];
    if (threadIdx.x < 16) s_b[threadIdx.x] = bias[threadIdx.x];

    const float* inb = in + (size_t)b * 3 * 1024;
    for (int i = threadIdx.x; i < 3 * 340; i += 256) {
        int c = i / 340, rem = i - c * 340;
        int r = rem / 34, col = rem - r * 34;
        int gy = y0 + r - 1, gx = col - 1;
        float v = 0.f;
        if ((unsigned)gy < 32u && (unsigned)gx < 32u) v = inb[c * 1024 + gy * 32 + gx];
        s_in[i] = v;
    }
    __syncthreads();

    float acc[16];
#pragma unroll
    for (int co = 0; co < 16; co++) acc[co] = s_b[co];
#pragma unroll
    for (int ci = 0; ci < 3; ci++) {
        float v[9];
#pragma unroll
        for (int dy = 0; dy < 3; dy++)
#pragma unroll
            for (int dx = 0; dx < 3; dx++)
                v[dy * 3 + dx] = s_in[ci * 340 + (ty + dy) * 34 + tx + dx];
#pragma unroll
        for (int co = 0; co < 16; co++)
#pragma unroll
            for (int k = 0; k < 9; k++)
                acc[co] = fmaf(v[k], s_w[(co * 3 + ci) * 9 + k], acc[co]);
    }
    float* outp = out + (size_t)b * 16 * 1024 + (y0 + ty) * 32 + tx;
#pragma unroll
    for (int co = 0; co < 16; co++) outp[co * 1024] = fmaxf(acc[co], 0.f);
}

// ---------------------------------------------------------------------------
// conv2 (16->8) + relu + fused fc partial dot.
// Writes g_part[b][chunk][j] (deterministic two-stage reduction).
// ---------------------------------------------------------------------------
__global__ __launch_bounds__(256) void conv2fc_kernel(
    const float* __restrict__ in, const float* __restrict__ w,
    const float* __restrict__ bias, const float* __restrict__ fcw,
    float* __restrict__ part)
{
    __shared__ float s_in[16 * 340];
    __shared__ float s_w[8 * 16 * 9];
    __shared__ float s_b[8];
    __shared__ float swp[8][4];

    const int b  = blockIdx.y;
    const int ck = blockIdx.x;
    const int y0 = ck * 8;
    const int tx = threadIdx.x & 31;
    const int ty = threadIdx.x >> 5;
    const int lane = tx;
    const int warp = ty;

    for (int i = threadIdx.x; i < 8 * 16 * 9; i += 256) s_w[i] = w[i];
    if (threadIdx.x < 8) s_b[threadIdx.x] = bias[threadIdx.x];

    const float* inb = in + (size_t)b * 16 * 1024;
    for (int i = threadIdx.x; i < 16 * 340; i += 256) {
        int c = i / 340, rem = i - c * 340;
        int r = rem / 34, col = rem - r * 34;
        int gy = y0 + r - 1, gx = col - 1;
        float v = 0.f;
        if ((unsigned)gy < 32u && (unsigned)gx < 32u) v = inb[c * 1024 + gy * 32 + gx];
        s_in[i] = v;
    }
    __syncthreads();

    float acc[8];
#pragma unroll
    for (int co = 0; co < 8; co++) acc[co] = s_b[co];
#pragma unroll
    for (int ci = 0; ci < 16; ci++) {
        float v[9];
#pragma unroll
        for (int dy = 0; dy < 3; dy++)
#pragma unroll
            for (int dx = 0; dx < 3; dx++)
                v[dy * 3 + dx] = s_in[ci * 340 + (ty + dy) * 34 + tx + dx];
#pragma unroll
        for (int co = 0; co < 8; co++)
#pragma unroll
            for (int k = 0; k < 9; k++)
                acc[co] = fmaf(v[k], s_w[(co * 16 + ci) * 9 + k], acc[co]);
    }

    // relu + fc partial dot:  k = c*1024 + y*32 + x
    const int y = y0 + ty;
    float p[4] = {0.f, 0.f, 0.f, 0.f};
#pragma unroll
    for (int c = 0; c < 8; c++) {
        float h = fmaxf(acc[c], 0.f);
        int k = c * 1024 + y * 32 + tx;
#pragma unroll
        for (int j = 0; j < 4; j++)
            p[j] = fmaf(h, fcw[j * 8192 + k], p[j]);
    }
#pragma unroll
    for (int off = 16; off > 0; off >>= 1)
#pragma unroll
        for (int j = 0; j < 4; j++)
            p[j] += __shfl_down_sync(0xffffffffu, p[j], off);
    if (lane == 0)
#pragma unroll
        for (int j = 0; j < 4; j++) swp[warp][j] = p[j];
    __syncthreads();
    if (threadIdx.x < 4) {
        float s = 0.f;
#pragma unroll
        for (int wq = 0; wq < 8; wq++) s += swp[wq][threadIdx.x];
        part[b * 16 + ck * 4 + threadIdx.x] = s;
    }
}

// ---------------------------------------------------------------------------
// Y build: Y[j] = dconv1(W_j), j=0..3 (W_j = fc2_w[:,j] as (8,32,32)),
//          Y[4] = dconv1(fc2_b img) + d1b.  No activation.
// ---------------------------------------------------------------------------
__global__ __launch_bounds__(256) void ybuild_kernel(
    const float* __restrict__ f2w, const float* __restrict__ f2b,
    const float* __restrict__ d1w, const float* __restrict__ d1b,
    float* __restrict__ Y)
{
    __shared__ float s_in[8 * 340];
    __shared__ float s_w[16 * 8 * 9];
    __shared__ float s_b[16];

    const int img = blockIdx.y;     // 0..4
    const int y0  = blockIdx.x * 8;
    const int tx = threadIdx.x & 31;
    const int ty = threadIdx.x >> 5;

    for (int i = threadIdx.x; i < 16 * 8 * 9; i += 256) s_w[i] = d1w[i];
    if (threadIdx.x < 16) s_b[threadIdx.x] = (img == 4) ? d1b[threadIdx.x] : 0.f;

    for (int i = threadIdx.x; i < 8 * 340; i += 256) {
        int c = i / 340, rem = i - c * 340;
        int r = rem / 34, col = rem - r * 34;
        int gy = y0 + r - 1, gx = col - 1;
        float v = 0.f;
        if ((unsigned)gy < 32u && (unsigned)gx < 32u) {
            int k = c * 1024 + gy * 32 + gx;
            v = (img < 4) ? f2w[(size_t)k * 4 + img] : f2b[k];
        }
        s_in[i] = v;
    }
    __syncthreads();

    float acc[16];
#pragma unroll
    for (int co = 0; co < 16; co++) acc[co] = s_b[co];
#pragma unroll
    for (int ci = 0; ci < 8; ci++) {
        float v[9];
#pragma unroll
        for (int dy = 0; dy < 3; dy++)
#pragma unroll
            for (int dx = 0; dx < 3; dx++)
                v[dy * 3 + dx] = s_in[ci * 340 + (ty + dy) * 34 + tx + dx];
#pragma unroll
        for (int co = 0; co < 16; co++)
#pragma unroll
            for (int k = 0; k < 9; k++)
                acc[co] = fmaf(v[k], s_w[(co * 8 + ci) * 9 + k], acc[co]);
    }
    float* outp = Y + img * 16384 + (y0 + ty) * 32 + tx;
#pragma unroll
    for (int co = 0; co < 16; co++) outp[co * 1024] = acc[co];
}

// ---------------------------------------------------------------------------
// Quantum: block precomputes the fixed entangling unitary V (16x16) in smem
// (16 threads simulate basis columns), then each thread handles one batch elt:
// ang = sum of fc partials + fcb; product state from RX; t = V s; expvals.
// ---------------------------------------------------------------------------
__device__ __forceinline__ float2 cmul(float2 a, float2 b) {
    return make_float2(a.x * b.x - a.y * b.y, a.x * b.y + a.y * b.x);
}

__global__ __launch_bounds__(256) void quantum_kernel(
    const float* __restrict__ part, const float* __restrict__ fcb,
    const float* __restrict__ qw, float* __restrict__ qout)
{
    __shared__ float2 sV[16][17];   // padded
    const int tid = threadIdx.x;

    if (tid < 16) {
        float2 st[16];
#pragma unroll
        for (int i = 0; i < 16; i++) st[i] = make_float2(0.f, 0.f);
        st[tid].x = 1.f;
#pragma unroll
        for (int l = 0; l < 3; l++) {
#pragma unroll
            for (int w = 0; w < 4; w++) {
                float phi = qw[(l * 4 + w) * 3 + 0];
                float th  = qw[(l * 4 + w) * 3 + 1];
                float om  = qw[(l * 4 + w) * 3 + 2];
                float ct = cosf(th * 0.5f), stt = sinf(th * 0.5f);
                float a = (phi + om) * 0.5f, d = (phi - om) * 0.5f;
                float ca = cosf(a), sa = sinf(a), cd = cosf(d), sd = sinf(d);
                float2 U00 = make_float2(ct * ca, -ct * sa);
                float2 U01 = make_float2(-stt * cd, -stt * sd);
                float2 U10 = make_float2(stt * cd, -stt * sd);
                float2 U11 = make_float2(ct * ca, ct * sa);
                const int bit = 1 << (3 - w);
#pragma unroll
                for (int i = 0; i < 16; i++) {
                    if (i & bit) continue;
                    float2 a0 = st[i], a1 = st[i | bit];
                    float2 n0 = cmul(U00, a0), n1 = cmul(U10, a0);
                    float2 m0 = cmul(U01, a1), m1 = cmul(U11, a1);
                    st[i]       = make_float2(n0.x + m0.x, n0.y + m0.y);
                    st[i | bit] = make_float2(n1.x + m1.x, n1.y + m1.y);
                }
            }
            const int r = (l % 3) + 1;
#pragma unroll
            for (int w = 0; w < 4; w++) {
                const int cb = 1 << (3 - w);
                const int tb = 1 << (3 - ((w + r) & 3));
#pragma unroll
                for (int i = 0; i < 16; i++) {
                    if ((i & cb) && !(i & tb)) {
                        float2 tmp = st[i]; st[i] = st[i | tb]; st[i | tb] = tmp;
                    }
                }
            }
        }
#pragma unroll
        for (int i = 0; i < 16; i++) sV[i][tid] = st[i];
    }
    __syncthreads();

    const int b = blockIdx.x * 256 + tid;
    if (b >= BATCH) return;

    float c[4], s[4];
#pragma unroll
    for (int w = 0; w < 4; w++) {
        float ang = part[b * 16 + 0 + w] + part[b * 16 + 4 + w]
                  + part[b * 16 + 8 + w] + part[b * 16 + 12 + w] + fcb[w];
        float half = ang * 0.5f;
        c[w] = cosf(half);
        s[w] = sinf(half);
    }

    // product state amp[i] = m_i * (-i)^popcount(i);  bit(3-w) <-> wire w
    float2 amp[16];
#pragma unroll
    for (int i = 0; i < 16; i++) {
        float m = ((i >> 3) & 1 ? s[0] : c[0]) * ((i >> 2) & 1 ? s[1] : c[1])
                * ((i >> 1) & 1 ? s[2] : c[2]) * ((i) & 1 ? s[3] : c[3]);
        int pc = __popc(i) & 3;
        amp[i] = (pc == 0) ? make_float2(m, 0.f)
               : (pc == 1) ? make_float2(0.f, -m)
               : (pc == 2) ? make_float2(-m, 0.f)
                           : make_float2(0.f, m);
    }

    float2 t[16];
#pragma unroll
    for (int i = 0; i < 16; i++) t[i] = make_float2(0.f, 0.f);
#pragma unroll
    for (int k = 0; k < 16; k++) {
        float2 a = amp[k];
#pragma unroll
        for (int i = 0; i < 16; i++) {
            float2 v = sV[i][k];
            t[i].x = fmaf(v.x, a.x, fmaf(-v.y, a.y, t[i].x));
            t[i].y = fmaf(v.x, a.y, fmaf(v.y, a.x, t[i].y));
        }
    }

    float p[16];
#pragma unroll
    for (int i = 0; i < 16; i++) p[i] = t[i].x * t[i].x + t[i].y * t[i].y;
#pragma unroll
    for (int w = 0; w < 4; w++) {
        const int bit = 1 << (3 - w);
        float ev = 0.f;
#pragma unroll
        for (int i = 0; i < 16; i++) ev += (i & bit) ? -p[i] : p[i];
        qout[b * 4 + w] = ev;
    }
}

// ---------------------------------------------------------------------------
// Fused output: h3 = relu(q0*Y0 + q1*Y1 + q2*Y2 + q3*Y3 + Ybase) built in smem
// (with halo), then dconv2 (16->3) + sigmoid -> out.
// ---------------------------------------------------------------------------
__global__ __launch_bounds__(256) void fused_out_kernel(
    const float* __restrict__ q, const float* __restrict__ Y,
    const float* __restrict__ w, const float* __restrict__ bias,
    float* __restrict__ out)
{
    __shared__ float s_h3[16 * 340];
    __shared__ float s_w[3 * 16 * 9];
    __shared__ float s_b[3];

    const int b  = blockIdx.y;
    const int y0 = blockIdx.x * 8;
    const int tx = threadIdx.x & 31;
    const int ty = threadIdx.x >> 5;

    for (int i = threadIdx.x; i < 3 * 16 * 9; i += 256) s_w[i] = w[i];
    if (threadIdx.x < 3) s_b[threadIdx.x] = bias[threadIdx.x];

    const float q0 = q[b * 4 + 0], q1 = q[b * 4 + 1];
    const float q2 = q[b * 4 + 2], q3 = q[b * 4 + 3];

    for (int i = threadIdx.x; i < 16 * 340; i += 256) {
        int c = i / 340, rem = i - c * 340;
        int r = rem / 34, col = rem - r * 34;
        int gy = y0 + r - 1, gx = col - 1;
        float v = 0.f;
        if ((unsigned)gy < 32u && (unsigned)gx < 32u) {
            int idx = c * 1024 + gy * 32 + gx;
            v = fmaf(q0, Y[idx],
                fmaf(q1, Y[16384 + idx],
                fmaf(q2, Y[32768 + idx],
                fmaf(q3, Y[49152 + idx], Y[65536 + idx]))));
            v = fmaxf(v, 0.f);
        }
        s_h3[i] = v;
    }
    __syncthreads();

    float acc[3];
#pragma unroll
    for (int co = 0; co < 3; co++) acc[co] = s_b[co];
#pragma unroll
    for (int ci = 0; ci < 16; ci++) {
        float v[9];
#pragma unroll
        for (int dy = 0; dy < 3; dy++)
#pragma unroll
            for (int dx = 0; dx < 3; dx++)
                v[dy * 3 + dx] = s_h3[ci * 340 + (ty + dy) * 34 + tx + dx];
#pragma unroll
        for (int co = 0; co < 3; co++)
#pragma unroll
            for (int k = 0; k < 9; k++)
                acc[co] = fmaf(v[k], s_w[(co * 16 + ci) * 9 + k], acc[co]);
    }
    float* outp = out + (size_t)b * 3 * 1024 + (y0 + ty) * 32 + tx;
#pragma unroll
    for (int co = 0; co < 3; co++)
        outp[co * 1024] = 1.f / (1.f + expf(-acc[co]));
}

// ---------------------------------------------------------------------------

extern "C" void kernel_launch(void* const* d_in, const int* in_sizes, int n_in,
                              void* d_out, int out_size)
{
    const float* x   = (const float*)d_in[0];
    const float* c1w = (const float*)d_in[1];
    const float* c1b = (const float*)d_in[2];
    const float* c2w = (const float*)d_in[3];
    const float* c2b = (const float*)d_in[4];
    const float* fcw = (const float*)d_in[5];
    const float* fcb = (const float*)d_in[6];
    const float* qw  = (const float*)d_in[7];
    const float* f2w = (const float*)d_in[8];
    const float* f2b = (const float*)d_in[9];
    const float* d1w = (const float*)d_in[10];
    const float* d1b = (const float*)d_in[11];
    const float* d2w = (const float*)d_in[12];
    const float* d2b = (const float*)d_in[13];
    float* out = (float*)d_out;

    float *h1, *part, *qv, *Y;
    cudaGetSymbolAddress((void**)&h1,   g_h1);
    cudaGetSymbolAddress((void**)&part, g_part);
    cudaGetSymbolAddress((void**)&qv,   g_q);
    cudaGetSymbolAddress((void**)&Y,    g_Y);

    dim3 cg(4, BATCH);
    conv1_kernel<<<cg, 256>>>(x, c1w, c1b, h1);
    ybuild_kernel<<<dim3(4, 5), 256>>>(f2w, f2b, d1w, d1b, Y);
    conv2fc_kernel<<<cg, 256>>>(h1, c2w, c2b, fcw, part);
    quantum_kernel<<<BATCH / 256, 256>>>(part, fcb, qw, qv);
    fused_out_kernel<<<cg, 256>>>(qv, Y, d2w, d2b, out);
}

// round 4
// speedup vs baseline: 2.2267x; 1.5589x over previous
#include <cuda_runtime.h>
#include <math.h>

#define BATCH 2048

// ---------------------------------------------------------------------------
// f32x2 packed helpers (sm_100+)
// ---------------------------------------------------------------------------
__device__ __forceinline__ unsigned long long pk2(float a, float b) {
    unsigned long long r;
    asm("mov.b64 %0, {%1, %2};" : "=l"(r) : "f"(a), "f"(b));
    return r;
}
__device__ __forceinline__ void upk2(unsigned long long v, float& a, float& b) {
    asm("mov.b64 {%0, %1}, %2;" : "=f"(a), "=f"(b) : "l"(v));
}
__device__ __forceinline__ unsigned long long fma2(
    unsigned long long a, unsigned long long b, unsigned long long c) {
    unsigned long long d;
    asm("fma.rn.f32x2 %0, %1, %2, %3;" : "=l"(d) : "l"(a), "l"(b), "l"(c));
    return d;
}

// ---------------------------------------------------------------------------
// Scratch (alloc-free device globals)
// ---------------------------------------------------------------------------
__device__ float g_h1[(size_t)BATCH * 16 * 1024];
__device__ float g_part[BATCH * 16];
__device__ float g_q[BATCH * 4];
__device__ float g_Y[5 * 16 * 1024];
__device__ float2 g_V[16 * 16];
__device__ float g_pkf[1512 * 2];    // packed weight pairs (lo,hi interleaved)
__device__ float g_pks[144];         // dconv2 scalar co=2 weights

// Constant weight banks (filled via captured D2D cudaMemcpyToSymbolAsync)
__constant__ unsigned long long c_w1[216];    // conv1:  [ci<3][k<9][p<8]
__constant__ unsigned long long c_w2[576];    // conv2:  [ci<16][k<9][p<4]
__constant__ unsigned long long c_wy[576];    // dconv1: [ci<8][k<9][p<8]
__constant__ unsigned long long c_wdp[144];   // dconv2: [ci<16][k<9] pair (co0,co1)
__constant__ float              c_wds[144];   // dconv2: [ci<16][k<9] co2

// ---------------------------------------------------------------------------
// Repack weights into (co,co+1)-paired layouts: [ci][k][pair]
// ---------------------------------------------------------------------------
__global__ __launch_bounds__(256) void repack_kernel(
    const float* __restrict__ c1w, const float* __restrict__ c2w,
    const float* __restrict__ d1w, const float* __restrict__ d2w)
{
    int i = blockIdx.x * 256 + threadIdx.x;
    if (i < 216) {                                  // conv1: 3*9*8 pairs
        int p = i & 7, t = i >> 3;
        int k = t % 9, ci = t / 9;
        g_pkf[2 * i]     = c1w[(2 * p) * 27 + ci * 9 + k];
        g_pkf[2 * i + 1] = c1w[(2 * p + 1) * 27 + ci * 9 + k];
    } else if (i < 792) {                           // conv2: 16*9*4 pairs
        int j = i - 216;
        int p = j & 3, t = j >> 2;
        int k = t % 9, ci = t / 9;
        g_pkf[2 * i]     = c2w[(2 * p) * 144 + ci * 9 + k];
        g_pkf[2 * i + 1] = c2w[(2 * p + 1) * 144 + ci * 9 + k];
    } else if (i < 1368) {                          // dconv1: 8*9*8 pairs
        int j = i - 792;
        int p = j & 7, t = j >> 3;
        int k = t % 9, ci = t / 9;
        g_pkf[2 * i]     = d1w[(2 * p) * 72 + ci * 9 + k];
        g_pkf[2 * i + 1] = d1w[(2 * p + 1) * 72 + ci * 9 + k];
    } else if (i < 1512) {                          // dconv2 pair (co0,co1)
        int j = i - 1368;
        int k = j % 9, ci = j / 9;
        g_pkf[2 * i]     = d2w[ci * 9 + k];
        g_pkf[2 * i + 1] = d2w[144 + ci * 9 + k];
    } else if (i < 1656) {                          // dconv2 scalar co2
        int j = i - 1512;
        int k = j % 9, ci = j / 9;
        g_pks[j] = d2w[288 + ci * 9 + k];
    }
}

// ---------------------------------------------------------------------------
// conv1: 3 -> 16, relu. Pairs over output channels.
// ---------------------------------------------------------------------------
__global__ __launch_bounds__(256) void conv1_kernel(
    const float* __restrict__ in, const float* __restrict__ bias,
    float* __restrict__ out)
{
    __shared__ float s_in[3 * 10 * 34];
    __shared__ float s_b[16];

    const int b  = blockIdx.y;
    const int y0 = blockIdx.x * 8;
    const int tx = threadIdx.x & 31;
    const int ty = threadIdx.x >> 5;

    if (threadIdx.x < 16) s_b[threadIdx.x] = bias[threadIdx.x];

    const float* inb = in + (size_t)b * 3 * 1024;
    for (int i = threadIdx.x; i < 3 * 340; i += 256) {
        int c = i / 340, rem = i - c * 340;
        int r = rem / 34, col = rem - r * 34;
        int gy = y0 + r - 1, gx = col - 1;
        float v = 0.f;
        if ((unsigned)gy < 32u && (unsigned)gx < 32u) v = inb[c * 1024 + gy * 32 + gx];
        s_in[i] = v;
    }
    __syncthreads();

    unsigned long long acc2[8];
#pragma unroll
    for (int p = 0; p < 8; p++) acc2[p] = pk2(s_b[2 * p], s_b[2 * p + 1]);

#pragma unroll
    for (int ci = 0; ci < 3; ci++) {
        float v[9];
#pragma unroll
        for (int dy = 0; dy < 3; dy++)
#pragma unroll
            for (int dx = 0; dx < 3; dx++)
                v[dy * 3 + dx] = s_in[ci * 340 + (ty + dy) * 34 + tx + dx];
#pragma unroll
        for (int k = 0; k < 9; k++) {
            unsigned long long vv = pk2(v[k], v[k]);
#pragma unroll
            for (int p = 0; p < 8; p++)
                acc2[p] = fma2(vv, c_w1[(ci * 9 + k) * 8 + p], acc2[p]);
        }
    }
    float* outp = out + (size_t)b * 16 * 1024 + (y0 + ty) * 32 + tx;
#pragma unroll
    for (int p = 0; p < 8; p++) {
        float lo, hi;
        upk2(acc2[p], lo, hi);
        outp[(2 * p) * 1024]     = fmaxf(lo, 0.f);
        outp[(2 * p + 1) * 1024] = fmaxf(hi, 0.f);
    }
}

// ---------------------------------------------------------------------------
// conv2 (16->8) + relu + fused fc partial dot -> g_part[b][chunk*4+j]
// ---------------------------------------------------------------------------
__global__ __launch_bounds__(256) void conv2fc_kernel(
    const float* __restrict__ in, const float* __restrict__ bias,
    const float* __restrict__ fcw, float* __restrict__ part)
{
    __shared__ float s_in[16 * 340];
    __shared__ float s_b[8];
    __shared__ float swp[8][4];

    const int b  = blockIdx.y;
    const int ck = blockIdx.x;
    const int y0 = ck * 8;
    const int tx = threadIdx.x & 31;
    const int ty = threadIdx.x >> 5;

    if (threadIdx.x < 8) s_b[threadIdx.x] = bias[threadIdx.x];

    const float* inb = in + (size_t)b * 16 * 1024;
    for (int i = threadIdx.x; i < 16 * 340; i += 256) {
        int c = i / 340, rem = i - c * 340;
        int r = rem / 34, col = rem - r * 34;
        int gy = y0 + r - 1, gx = col - 1;
        float v = 0.f;
        if ((unsigned)gy < 32u && (unsigned)gx < 32u) v = inb[c * 1024 + gy * 32 + gx];
        s_in[i] = v;
    }
    __syncthreads();

    unsigned long long acc2[4];
#pragma unroll
    for (int p = 0; p < 4; p++) acc2[p] = pk2(s_b[2 * p], s_b[2 * p + 1]);

#pragma unroll
    for (int ci = 0; ci < 16; ci++) {
        float v[9];
#pragma unroll
        for (int dy = 0; dy < 3; dy++)
#pragma unroll
            for (int dx = 0; dx < 3; dx++)
                v[dy * 3 + dx] = s_in[ci * 340 + (ty + dy) * 34 + tx + dx];
#pragma unroll
        for (int k = 0; k < 9; k++) {
            unsigned long long vv = pk2(v[k], v[k]);
#pragma unroll
            for (int p = 0; p < 4; p++)
                acc2[p] = fma2(vv, c_w2[(ci * 9 + k) * 4 + p], acc2[p]);
        }
    }

    // relu + fc partial dot  (k = c*1024 + y*32 + x)
    const int y = y0 + ty;
    float h[8];
#pragma unroll
    for (int p = 0; p < 4; p++) {
        float lo, hi;
        upk2(acc2[p], lo, hi);
        h[2 * p]     = fmaxf(lo, 0.f);
        h[2 * p + 1] = fmaxf(hi, 0.f);
    }
    float pr[4] = {0.f, 0.f, 0.f, 0.f};
#pragma unroll
    for (int c = 0; c < 8; c++) {
        int k = c * 1024 + y * 32 + tx;
#pragma unroll
        for (int j = 0; j < 4; j++)
            pr[j] = fmaf(h[c], __ldg(fcw + j * 8192 + k), pr[j]);
    }
#pragma unroll
    for (int off = 16; off > 0; off >>= 1)
#pragma unroll
        for (int j = 0; j < 4; j++)
            pr[j] += __shfl_down_sync(0xffffffffu, pr[j], off);
    if (tx == 0)
#pragma unroll
        for (int j = 0; j < 4; j++) swp[ty][j] = pr[j];
    __syncthreads();
    if (threadIdx.x < 4) {
        float s = 0.f;
#pragma unroll
        for (int wq = 0; wq < 8; wq++) s += swp[wq][threadIdx.x];
        part[b * 16 + ck * 4 + threadIdx.x] = s;
    }
}

// ---------------------------------------------------------------------------
// Y build: Y[j] = dconv1(fc2_w[:,j]) j=0..3;  Y[4] = dconv1(fc2_b) + d1b.
// ---------------------------------------------------------------------------
__global__ __launch_bounds__(256) void ybuild_kernel(
    const float* __restrict__ f2w, const float* __restrict__ f2b,
    const float* __restrict__ d1b, float* __restrict__ Y)
{
    __shared__ float s_in[8 * 340];
    __shared__ float s_b[16];

    const int img = blockIdx.y;
    const int y0  = blockIdx.x * 8;
    const int tx = threadIdx.x & 31;
    const int ty = threadIdx.x >> 5;

    if (threadIdx.x < 16) s_b[threadIdx.x] = (img == 4) ? d1b[threadIdx.x] : 0.f;

    for (int i = threadIdx.x; i < 8 * 340; i += 256) {
        int c = i / 340, rem = i - c * 340;
        int r = rem / 34, col = rem - r * 34;
        int gy = y0 + r - 1, gx = col - 1;
        float v = 0.f;
        if ((unsigned)gy < 32u && (unsigned)gx < 32u) {
            int k = c * 1024 + gy * 32 + gx;
            v = (img < 4) ? f2w[(size_t)k * 4 + img] : f2b[k];
        }
        s_in[i] = v;
    }
    __syncthreads();

    unsigned long long acc2[8];
#pragma unroll
    for (int p = 0; p < 8; p++) acc2[p] = pk2(s_b[2 * p], s_b[2 * p + 1]);

#pragma unroll
    for (int ci = 0; ci < 8; ci++) {
        float v[9];
#pragma unroll
        for (int dy = 0; dy < 3; dy++)
#pragma unroll
            for (int dx = 0; dx < 3; dx++)
                v[dy * 3 + dx] = s_in[ci * 340 + (ty + dy) * 34 + tx + dx];
#pragma unroll
        for (int k = 0; k < 9; k++) {
            unsigned long long vv = pk2(v[k], v[k]);
#pragma unroll
            for (int p = 0; p < 8; p++)
                acc2[p] = fma2(vv, c_wy[(ci * 9 + k) * 8 + p], acc2[p]);
        }
    }
    float* outp = Y + img * 16384 + (y0 + ty) * 32 + tx;
#pragma unroll
    for (int p = 0; p < 8; p++) {
        float lo, hi;
        upk2(acc2[p], lo, hi);
        outp[(2 * p) * 1024]     = lo;
        outp[(2 * p + 1) * 1024] = hi;
    }
}

// ---------------------------------------------------------------------------
// V build: fixed 16x16 entangling unitary, one block of 16 threads.
// ---------------------------------------------------------------------------
__device__ __forceinline__ float2 cmul(float2 a, float2 b) {
    return make_float2(a.x * b.x - a.y * b.y, a.x * b.y + a.y * b.x);
}

__global__ void vbuild_kernel(const float* __restrict__ qw, float2* __restrict__ V)
{
    const int tid = threadIdx.x;   // basis column
    float2 st[16];
#pragma unroll
    for (int i = 0; i < 16; i++) st[i] = make_float2(0.f, 0.f);
    st[tid].x = 1.f;

#pragma unroll
    for (int l = 0; l < 3; l++) {
#pragma unroll
        for (int w = 0; w < 4; w++) {
            float phi = qw[(l * 4 + w) * 3 + 0];
            float th  = qw[(l * 4 + w) * 3 + 1];
            float om  = qw[(l * 4 + w) * 3 + 2];
            float ct = cosf(th * 0.5f), stt = sinf(th * 0.5f);
            float a = (phi + om) * 0.5f, d = (phi - om) * 0.5f;
            float ca = cosf(a), sa = sinf(a), cd = cosf(d), sd = sinf(d);
            float2 U00 = make_float2(ct * ca, -ct * sa);
            float2 U01 = make_float2(-stt * cd, -stt * sd);
            float2 U10 = make_float2(stt * cd, -stt * sd);
            float2 U11 = make_float2(ct * ca, ct * sa);
            const int bit = 1 << (3 - w);
#pragma unroll
            for (int i = 0; i < 16; i++) {
                if (i & bit) continue;
                float2 a0 = st[i], a1 = st[i | bit];
                float2 n0 = cmul(U00, a0), n1 = cmul(U10, a0);
                float2 m0 = cmul(U01, a1), m1 = cmul(U11, a1);
                st[i]       = make_float2(n0.x + m0.x, n0.y + m0.y);
                st[i | bit] = make_float2(n1.x + m1.x, n1.y + m1.y);
            }
        }
        const int r = (l % 3) + 1;
#pragma unroll
        for (int w = 0; w < 4; w++) {
            const int cb = 1 << (3 - w);
            const int tb = 1 << (3 - ((w + r) & 3));
#pragma unroll
            for (int i = 0; i < 16; i++) {
                if ((i & cb) && !(i & tb)) {
                    float2 tmp = st[i]; st[i] = st[i | tb]; st[i | tb] = tmp;
                }
            }
        }
    }
#pragma unroll
    for (int i = 0; i < 16; i++) V[i * 16 + tid] = st[i];
}

// ---------------------------------------------------------------------------
// Quantum batched: ang = sum partials + fcb; product state; t = V s; expvals.
// ---------------------------------------------------------------------------
__global__ __launch_bounds__(128) void quantum_kernel(
    const float* __restrict__ part, const float* __restrict__ fcb,
    const float2* __restrict__ V, float* __restrict__ qout)
{
    __shared__ float2 sV[256];
    for (int i = threadIdx.x; i < 256; i += 128) sV[i] = V[i];
    __syncthreads();

    const int b = blockIdx.x * 128 + threadIdx.x;

    float c[4], s[4];
#pragma unroll
    for (int w = 0; w < 4; w++) {
        float ang = part[b * 16 + 0 + w] + part[b * 16 + 4 + w]
                  + part[b * 16 + 8 + w] + part[b * 16 + 12 + w] + fcb[w];
        float half = ang * 0.5f;
        c[w] = cosf(half);
        s[w] = sinf(half);
    }

    float2 amp[16];
#pragma unroll
    for (int i = 0; i < 16; i++) {
        float m = ((i >> 3) & 1 ? s[0] : c[0]) * ((i >> 2) & 1 ? s[1] : c[1])
                * ((i >> 1) & 1 ? s[2] : c[2]) * ((i) & 1 ? s[3] : c[3]);
        int pc = __popc(i) & 3;
        amp[i] = (pc == 0) ? make_float2(m, 0.f)
               : (pc == 1) ? make_float2(0.f, -m)
               : (pc == 2) ? make_float2(-m, 0.f)
                           : make_float2(0.f, m);
    }

    float2 t[16];
#pragma unroll
    for (int i = 0; i < 16; i++) t[i] = make_float2(0.f, 0.f);
#pragma unroll
    for (int k = 0; k < 16; k++) {
        float2 a = amp[k];
#pragma unroll
        for (int i = 0; i < 16; i++) {
            float2 v = sV[i * 16 + k];
            t[i].x = fmaf(v.x, a.x, fmaf(-v.y, a.y, t[i].x));
            t[i].y = fmaf(v.x, a.y, fmaf(v.y, a.x, t[i].y));
        }
    }

    float p[16];
#pragma unroll
    for (int i = 0; i < 16; i++) p[i] = t[i].x * t[i].x + t[i].y * t[i].y;
#pragma unroll
    for (int w = 0; w < 4; w++) {
        const int bit = 1 << (3 - w);
        float ev = 0.f;
#pragma unroll
        for (int i = 0; i < 16; i++) ev += (i & bit) ? -p[i] : p[i];
        qout[b * 4 + w] = ev;
    }
}

// ---------------------------------------------------------------------------
// Fused output: h3 = relu(sum q_j Y_j + Ybase) in smem, then dconv2 + sigmoid.
// ---------------------------------------------------------------------------
__global__ __launch_bounds__(256) void fused_out_kernel(
    const float* __restrict__ q, const float* __restrict__ Y,
    const float* __restrict__ bias, float* __restrict__ out)
{
    __shared__ float s_h3[16 * 340];
    __shared__ float s_b[3];

    const int b  = blockIdx.y;
    const int y0 = blockIdx.x * 8;
    const int tx = threadIdx.x & 31;
    const int ty = threadIdx.x >> 5;

    if (threadIdx.x < 3) s_b[threadIdx.x] = bias[threadIdx.x];

    const float q0 = q[b * 4 + 0], q1 = q[b * 4 + 1];
    const float q2 = q[b * 4 + 2], q3 = q[b * 4 + 3];

    for (int i = threadIdx.x; i < 16 * 340; i += 256) {
        int c = i / 340, rem = i - c * 340;
        int r = rem / 34, col = rem - r * 34;
        int gy = y0 + r - 1, gx = col - 1;
        float v = 0.f;
        if ((unsigned)gy < 32u && (unsigned)gx < 32u) {
            int idx = c * 1024 + gy * 32 + gx;
            v = fmaf(q0, Y[idx],
                fmaf(q1, Y[16384 + idx],
                fmaf(q2, Y[32768 + idx],
                fmaf(q3, Y[49152 + idx], Y[65536 + idx]))));
            v = fmaxf(v, 0.f);
        }
        s_h3[i] = v;
    }
    __syncthreads();

    unsigned long long acc2 = pk2(s_b[0], s_b[1]);
    float acc = s_b[2];
#pragma unroll
    for (int ci = 0; ci < 16; ci++) {
        float v[9];
#pragma unroll
        for (int dy = 0; dy < 3; dy++)
#pragma unroll
            for (int dx = 0; dx < 3; dx++)
                v[dy * 3 + dx] = s_h3[ci * 340 + (ty + dy) * 34 + tx + dx];
#pragma unroll
        for (int k = 0; k < 9; k++) {
            unsigned long long vv = pk2(v[k], v[k]);
            acc2 = fma2(vv, c_wdp[ci * 9 + k], acc2);
            acc  = fmaf(v[k], c_wds[ci * 9 + k], acc);
        }
    }
    float r0, r1;
    upk2(acc2, r0, r1);
    float* outp = out + (size_t)b * 3 * 1024 + (y0 + ty) * 32 + tx;
    outp[0]    = __fdividef(1.f, 1.f + __expf(-r0));
    outp[1024] = __fdividef(1.f, 1.f + __expf(-r1));
    outp[2048] = __fdividef(1.f, 1.f + __expf(-acc));
}

// ---------------------------------------------------------------------------

extern "C" void kernel_launch(void* const* d_in, const int* in_sizes, int n_in,
                              void* d_out, int out_size)
{
    const float* x   = (const float*)d_in[0];
    const float* c1w = (const float*)d_in[1];
    const float* c1b = (const float*)d_in[2];
    const float* c2w = (const float*)d_in[3];
    const float* c2b = (const float*)d_in[4];
    const float* fcw = (const float*)d_in[5];
    const float* fcb = (const float*)d_in[6];
    const float* qw  = (const float*)d_in[7];
    const float* f2w = (const float*)d_in[8];
    const float* f2b = (const float*)d_in[9];
    const float* d1w = (const float*)d_in[10];
    const float* d1b = (const float*)d_in[11];
    const float* d2w = (const float*)d_in[12];
    const float* d2b = (const float*)d_in[13];
    float* out = (float*)d_out;

    float *h1, *part, *qv, *Y, *pkf, *pks;
    float2* V;
    cudaGetSymbolAddress((void**)&h1,   g_h1);
    cudaGetSymbolAddress((void**)&part, g_part);
    cudaGetSymbolAddress((void**)&qv,   g_q);
    cudaGetSymbolAddress((void**)&Y,    g_Y);
    cudaGetSymbolAddress((void**)&V,    g_V);
    cudaGetSymbolAddress((void**)&pkf,  g_pkf);
    cudaGetSymbolAddress((void**)&pks,  g_pks);

    repack_kernel<<<7, 256>>>(c1w, c2w, d1w, d2w);
    cudaMemcpyToSymbolAsync(c_w1,  pkf,            216 * 8, 0, cudaMemcpyDeviceToDevice, 0);
    cudaMemcpyToSymbolAsync(c_w2,  pkf + 216 * 2,  576 * 8, 0, cudaMemcpyDeviceToDevice, 0);
    cudaMemcpyToSymbolAsync(c_wy,  pkf + 792 * 2,  576 * 8, 0, cudaMemcpyDeviceToDevice, 0);
    cudaMemcpyToSymbolAsync(c_wdp, pkf + 1368 * 2, 144 * 8, 0, cudaMemcpyDeviceToDevice, 0);
    cudaMemcpyToSymbolAsync(c_wds, pks,            144 * 4, 0, cudaMemcpyDeviceToDevice, 0);

    vbuild_kernel<<<1, 16>>>(qw, V);

    dim3 cg(4, BATCH);
    conv1_kernel<<<cg, 256>>>(x, c1b, h1);
    ybuild_kernel<<<dim3(4, 5), 256>>>(f2w, f2b, d1b, Y);
    conv2fc_kernel<<<cg, 256>>>(h1, c2b, fcw, part);
    quantum_kernel<<<BATCH / 128, 128>>>(part, fcb, V, qv);
    fused_out_kernel<<<cg, 256>>>(qv, Y, d2b, out);
}

// round 5
// speedup vs baseline: 2.7550x; 1.2373x over previous
#include <cuda_runtime.h>
#include <math.h>

#define BATCH 2048
typedef unsigned long long ull;

// ---------------------------------------------------------------------------
// f32x2 packed helpers (sm_100+)
// ---------------------------------------------------------------------------
__device__ __forceinline__ ull pk2(float a, float b) {
    ull r;
    asm("mov.b64 %0, {%1, %2};" : "=l"(r) : "f"(a), "f"(b));
    return r;
}
__device__ __forceinline__ void upk2(ull v, float& a, float& b) {
    asm("mov.b64 {%0, %1}, %2;" : "=f"(a), "=f"(b) : "l"(v));
}
__device__ __forceinline__ ull fma2(ull a, ull b, ull c) {
    ull d;
    asm("fma.rn.f32x2 %0, %1, %2, %3;" : "=l"(d) : "l"(a), "l"(b), "l"(c));
    return d;
}

// ---------------------------------------------------------------------------
// Packed weight bank: single struct so ONE symbol copy suffices.
// ---------------------------------------------------------------------------
struct CW {
    ull w1[216];     // conv1  [ci<3 ][k<9][p<8]  pairs (co=2p,2p+1)
    ull w2[576];     // conv2  [ci<16][k<9][p<4]
    ull wy[576];     // dconv1 [ci<8 ][k<9][p<8]
    ull wdp[144];    // dconv2 [ci<16][k<9]  pair (co0,co1)
    float wds[144];  // dconv2 [ci<16][k<9]  co2
};
__device__ CW g_pk;
__constant__ CW c_w;

// Scratch (alloc-free device globals)
__device__ float g_part[BATCH * 16];
__device__ float g_q[BATCH * 4];
__device__ float g_Y[5 * 16 * 1024];
__device__ float2 g_V[256];

// ---------------------------------------------------------------------------
// Repack weights + build fixed 16x16 entangling unitary (block 7).
// ---------------------------------------------------------------------------
__device__ __forceinline__ float2 cmul(float2 a, float2 b) {
    return make_float2(a.x * b.x - a.y * b.y, a.x * b.y + a.y * b.x);
}

__global__ __launch_bounds__(256) void setup_kernel(
    const float* __restrict__ c1w, const float* __restrict__ c2w,
    const float* __restrict__ d1w, const float* __restrict__ d2w,
    const float* __restrict__ qw, float2* __restrict__ V)
{
    if (blockIdx.x == 7) {
        // --- vbuild: 16 threads simulate basis columns ---
        const int tid = threadIdx.x;
        if (tid >= 16) return;
        float2 st[16];
#pragma unroll
        for (int i = 0; i < 16; i++) st[i] = make_float2(0.f, 0.f);
        st[tid].x = 1.f;
#pragma unroll
        for (int l = 0; l < 3; l++) {
#pragma unroll
            for (int w = 0; w < 4; w++) {
                float phi = qw[(l * 4 + w) * 3 + 0];
                float th  = qw[(l * 4 + w) * 3 + 1];
                float om  = qw[(l * 4 + w) * 3 + 2];
                float ct = cosf(th * 0.5f), stt = sinf(th * 0.5f);
                float a = (phi + om) * 0.5f, d = (phi - om) * 0.5f;
                float ca = cosf(a), sa = sinf(a), cd = cosf(d), sd = sinf(d);
                float2 U00 = make_float2(ct * ca, -ct * sa);
                float2 U01 = make_float2(-stt * cd, -stt * sd);
                float2 U10 = make_float2(stt * cd, -stt * sd);
                float2 U11 = make_float2(ct * ca, ct * sa);
                const int bit = 1 << (3 - w);
#pragma unroll
                for (int i = 0; i < 16; i++) {
                    if (i & bit) continue;
                    float2 a0 = st[i], a1 = st[i | bit];
                    float2 n0 = cmul(U00, a0), n1 = cmul(U10, a0);
                    float2 m0 = cmul(U01, a1), m1 = cmul(U11, a1);
                    st[i]       = make_float2(n0.x + m0.x, n0.y + m0.y);
                    st[i | bit] = make_float2(n1.x + m1.x, n1.y + m1.y);
                }
            }
            const int r = (l % 3) + 1;
#pragma unroll
            for (int w = 0; w < 4; w++) {
                const int cb = 1 << (3 - w);
                const int tb = 1 << (3 - ((w + r) & 3));
#pragma unroll
                for (int i = 0; i < 16; i++) {
                    if ((i & cb) && !(i & tb)) {
                        float2 tmp = st[i]; st[i] = st[i | tb]; st[i | tb] = tmp;
                    }
                }
            }
        }
#pragma unroll
        for (int i = 0; i < 16; i++) V[i * 16 + tid] = st[i];
        return;
    }

    int i = blockIdx.x * 256 + threadIdx.x;
    float* w1f  = (float*)g_pk.w1;
    float* w2f  = (float*)g_pk.w2;
    float* wyf  = (float*)g_pk.wy;
    float* wdpf = (float*)g_pk.wdp;
    if (i < 216) {                                  // conv1: 3*9*8 pairs
        int p = i & 7, t = i >> 3;
        int k = t % 9, ci = t / 9;
        w1f[2 * i]     = c1w[(2 * p) * 27 + ci * 9 + k];
        w1f[2 * i + 1] = c1w[(2 * p + 1) * 27 + ci * 9 + k];
    } else if (i < 792) {                           // conv2: 16*9*4 pairs
        int j = i - 216;
        int p = j & 3, t = j >> 2;
        int k = t % 9, ci = t / 9;
        w2f[2 * j]     = c2w[(2 * p) * 144 + ci * 9 + k];
        w2f[2 * j + 1] = c2w[(2 * p + 1) * 144 + ci * 9 + k];
    } else if (i < 1368) {                          // dconv1: 8*9*8 pairs
        int j = i - 792;
        int p = j & 7, t = j >> 3;
        int k = t % 9, ci = t / 9;
        wyf[2 * j]     = d1w[(2 * p) * 72 + ci * 9 + k];
        wyf[2 * j + 1] = d1w[(2 * p + 1) * 72 + ci * 9 + k];
    } else if (i < 1512) {                          // dconv2 pair (co0,co1)
        int j = i - 1368;
        int k = j % 9, ci = j / 9;
        wdpf[2 * j]     = d2w[ci * 9 + k];
        wdpf[2 * j + 1] = d2w[144 + ci * 9 + k];
    } else if (i < 1656) {                          // dconv2 scalar co2
        int j = i - 1512;
        int k = j % 9, ci = j / 9;
        g_pk.wds[j] = d2w[288 + ci * 9 + k];
    }
}

// ---------------------------------------------------------------------------
// Fused conv1 (3->16, relu, into smem incl. row/col halo) + conv2 (16->8, relu)
// + fc partial dot. Block = 320 threads, one image x 8 output rows.
// ---------------------------------------------------------------------------
__global__ __launch_bounds__(320) void conv12_kernel(
    const float* __restrict__ in, const float* __restrict__ b1,
    const float* __restrict__ b2, const float* __restrict__ fcw,
    float* __restrict__ part)
{
    __shared__ float s_x[3 * 12 * 34];     // 12 rows x 34 cols, zero-padded
    __shared__ float s_h1[16 * 10 * 34];   // h1 tile: 10 rows (+row halo), 34 cols
    __shared__ float s_b1[16];
    __shared__ float s_b2[8];
    __shared__ float swp[8][4];

    const int b  = blockIdx.y;
    const int ck = blockIdx.x;
    const int y0 = ck * 8;
    const int tid = threadIdx.x;

    if (tid < 16) s_b1[tid] = b1[tid];
    else if (tid < 24) s_b2[tid - 16] = b2[tid - 16];

    // load x tile: rows y0-2 .. y0+9, cols -1..32
    const float* inb = in + (size_t)b * 3 * 1024;
    for (int i = tid; i < 3 * 408; i += 320) {
        int c = i / 408, rem = i - c * 408;
        int r = rem / 34, xc = rem - r * 34;
        int gy = y0 - 2 + r, gx = xc - 1;
        float v = 0.f;
        if ((unsigned)gy < 32u && (unsigned)gx < 32u) v = inb[c * 1024 + gy * 32 + gx];
        s_x[i] = v;
    }
    __syncthreads();

    // conv1 phase: 320 threads = 10 h1-rows x 32 cols
    {
        const int hr = tid >> 5, col = tid & 31;
        const int gy = y0 - 1 + hr;
        // zero col halo (threads col 0/1 handle xc=0 / xc=33 for their row)
        if (col < 2) {
            int xc = (col == 0) ? 0 : 33;
#pragma unroll
            for (int c = 0; c < 16; c++) s_h1[c * 340 + hr * 34 + xc] = 0.f;
        }
        if ((unsigned)gy < 32u) {
            ull acc2[8];
#pragma unroll
            for (int p = 0; p < 8; p++) acc2[p] = pk2(s_b1[2 * p], s_b1[2 * p + 1]);
#pragma unroll
            for (int ci = 0; ci < 3; ci++) {
                float v[9];
#pragma unroll
                for (int dy = 0; dy < 3; dy++)
#pragma unroll
                    for (int dx = 0; dx < 3; dx++)
                        v[dy * 3 + dx] = s_x[ci * 408 + (hr + dy) * 34 + col + dx];
#pragma unroll
                for (int k = 0; k < 9; k++) {
                    ull vv = pk2(v[k], v[k]);
#pragma unroll
                    for (int p = 0; p < 8; p++)
                        acc2[p] = fma2(vv, c_w.w1[(ci * 9 + k) * 8 + p], acc2[p]);
                }
            }
#pragma unroll
            for (int p = 0; p < 8; p++) {
                float lo, hi;
                upk2(acc2[p], lo, hi);
                s_h1[(2 * p) * 340 + hr * 34 + col + 1]     = fmaxf(lo, 0.f);
                s_h1[(2 * p + 1) * 340 + hr * 34 + col + 1] = fmaxf(hi, 0.f);
            }
        } else {
#pragma unroll
            for (int c = 0; c < 16; c++) s_h1[c * 340 + hr * 34 + col + 1] = 0.f;
        }
    }
    __syncthreads();

    // conv2 phase: threads 0..255 = 8 rows x 32 cols
    if (tid < 256) {
        const int tx = tid & 31, ty = tid >> 5;
        ull acc2[4];
#pragma unroll
        for (int p = 0; p < 4; p++) acc2[p] = pk2(s_b2[2 * p], s_b2[2 * p + 1]);
#pragma unroll
        for (int ci = 0; ci < 16; ci++) {
            float v[9];
#pragma unroll
            for (int dy = 0; dy < 3; dy++)
#pragma unroll
                for (int dx = 0; dx < 3; dx++)
                    v[dy * 3 + dx] = s_h1[ci * 340 + (ty + dy) * 34 + tx + dx];
#pragma unroll
            for (int k = 0; k < 9; k++) {
                ull vv = pk2(v[k], v[k]);
#pragma unroll
                for (int p = 0; p < 4; p++)
                    acc2[p] = fma2(vv, c_w.w2[(ci * 9 + k) * 4 + p], acc2[p]);
            }
        }
        // relu + fc partial dot  (k = c*1024 + y*32 + x)
        const int y = y0 + ty;
        float h[8];
#pragma unroll
        for (int p = 0; p < 4; p++) {
            float lo, hi;
            upk2(acc2[p], lo, hi);
            h[2 * p]     = fmaxf(lo, 0.f);
            h[2 * p + 1] = fmaxf(hi, 0.f);
        }
        float pr[4] = {0.f, 0.f, 0.f, 0.f};
#pragma unroll
        for (int c = 0; c < 8; c++) {
            int k = c * 1024 + y * 32 + tx;
#pragma unroll
            for (int j = 0; j < 4; j++)
                pr[j] = fmaf(h[c], __ldg(fcw + j * 8192 + k), pr[j]);
        }
#pragma unroll
        for (int off = 16; off > 0; off >>= 1)
#pragma unroll
            for (int j = 0; j < 4; j++)
                pr[j] += __shfl_down_sync(0xffffffffu, pr[j], off);
        if (tx == 0)
#pragma unroll
            for (int j = 0; j < 4; j++) swp[ty][j] = pr[j];
    }
    __syncthreads();
    if (tid < 4) {
        float s = 0.f;
#pragma unroll
        for (int wq = 0; wq < 8; wq++) s += swp[wq][tid];
        part[b * 16 + ck * 4 + tid] = s;
    }
}

// ---------------------------------------------------------------------------
// Y build: one thread per (img, pixel, channel-pair). 160 blocks.
// Y[j] = dconv1(fc2_w[:,j]) j=0..3;  Y[4] = dconv1(fc2_b) + d1b.
// ---------------------------------------------------------------------------
__global__ __launch_bounds__(256) void ybuild_kernel(
    const float* __restrict__ f2w, const float* __restrict__ f2b,
    const float* __restrict__ d1b, float* __restrict__ Y)
{
    const int idx  = blockIdx.x * 256 + threadIdx.x;   // < 40960
    const int px   = idx & 1023;
    const int pair = (idx >> 10) & 7;
    const int img  = idx >> 13;
    const int y = px >> 5, x = px & 31;

    ull acc = (img == 4) ? pk2(d1b[2 * pair], d1b[2 * pair + 1]) : pk2(0.f, 0.f);
#pragma unroll
    for (int ci = 0; ci < 8; ci++) {
#pragma unroll
        for (int dy = 0; dy < 3; dy++) {
            int gy = y + dy - 1;
            if ((unsigned)gy >= 32u) continue;
#pragma unroll
            for (int dx = 0; dx < 3; dx++) {
                int gx = x + dx - 1;
                if ((unsigned)gx >= 32u) continue;
                int k = ci * 1024 + gy * 32 + gx;
                float v = (img < 4) ? __ldg(f2w + (size_t)k * 4 + img) : __ldg(f2b + k);
                acc = fma2(pk2(v, v), c_w.wy[(ci * 9 + dy * 3 + dx) * 8 + pair], acc);
            }
        }
    }
    float lo, hi;
    upk2(acc, lo, hi);
    Y[img * 16384 + (2 * pair) * 1024 + px]     = lo;
    Y[img * 16384 + (2 * pair + 1) * 1024 + px] = hi;
}

// ---------------------------------------------------------------------------
// Quantum batched: ang = sum partials + fcb; product state; t = V s; expvals.
// ---------------------------------------------------------------------------
__global__ __launch_bounds__(128) void quantum_kernel(
    const float* __restrict__ part, const float* __restrict__ fcb,
    const float2* __restrict__ V, float* __restrict__ qout)
{
    __shared__ float2 sV[256];
    for (int i = threadIdx.x; i < 256; i += 128) sV[i] = V[i];
    __syncthreads();

    const int b = blockIdx.x * 128 + threadIdx.x;

    float c[4], s[4];
#pragma unroll
    for (int w = 0; w < 4; w++) {
        float ang = part[b * 16 + 0 + w] + part[b * 16 + 4 + w]
                  + part[b * 16 + 8 + w] + part[b * 16 + 12 + w] + fcb[w];
        float half = ang * 0.5f;
        c[w] = cosf(half);
        s[w] = sinf(half);
    }

    float2 amp[16];
#pragma unroll
    for (int i = 0; i < 16; i++) {
        float m = ((i >> 3) & 1 ? s[0] : c[0]) * ((i >> 2) & 1 ? s[1] : c[1])
                * ((i >> 1) & 1 ? s[2] : c[2]) * ((i) & 1 ? s[3] : c[3]);
        int pc = __popc(i) & 3;
        amp[i] = (pc == 0) ? make_float2(m, 0.f)
               : (pc == 1) ? make_float2(0.f, -m)
               : (pc == 2) ? make_float2(-m, 0.f)
                           : make_float2(0.f, m);
    }

    float2 t[16];
#pragma unroll
    for (int i = 0; i < 16; i++) t[i] = make_float2(0.f, 0.f);
#pragma unroll
    for (int k = 0; k < 16; k++) {
        float2 a = amp[k];
#pragma unroll
        for (int i = 0; i < 16; i++) {
            float2 v = sV[i * 16 + k];
            t[i].x = fmaf(v.x, a.x, fmaf(-v.y, a.y, t[i].x));
            t[i].y = fmaf(v.x, a.y, fmaf(v.y, a.x, t[i].y));
        }
    }

    float p[16];
#pragma unroll
    for (int i = 0; i < 16; i++) p[i] = t[i].x * t[i].x + t[i].y * t[i].y;
#pragma unroll
    for (int w = 0; w < 4; w++) {
        const int bit = 1 << (3 - w);
        float ev = 0.f;
#pragma unroll
        for (int i = 0; i < 16; i++) ev += (i & bit) ? -p[i] : p[i];
        qout[b * 4 + w] = ev;
    }
}

// ---------------------------------------------------------------------------
// Fused output, batch-grouped: block loads Y tile (5 img x 16ch x 10x34) into
// dynamic smem ONCE, then serves 16 batch elements (2 per iter, 512 threads).
// h3 = relu(sum q_j Y_j + Ybase); dconv2 (16->3) + sigmoid.
// ---------------------------------------------------------------------------
#define YTILE 5440            // 16*340
__global__ __launch_bounds__(512) void fused_out_kernel(
    const float* __restrict__ q, const float* __restrict__ Y,
    const float* __restrict__ bias, float* __restrict__ out)
{
    extern __shared__ float smem[];
    float* sY = smem;               // 5 * 5440
    float* sH = smem + 5 * YTILE;   // 2 * 5440

    const int ck = blockIdx.x;
    const int y0 = ck * 8;
    const int b0 = blockIdx.y * 16;
    const int tid  = threadIdx.x;
    const int half = tid >> 8;
    const int htid = tid & 255;

    __shared__ float s_b[3];
    if (tid < 3) s_b[tid] = bias[tid];

    // Load Y tile: rows y0-1..y0+8, cols -1..32 (zero outside image)
    for (int i = tid; i < 5 * YTILE; i += 512) {
        int img = i / YTILE, rem = i - img * YTILE;
        int c = rem / 340, rem2 = rem - c * 340;
        int r = rem2 / 34, xc = rem2 - r * 34;
        int gy = y0 + r - 1, gx = xc - 1;
        float v = 0.f;
        if ((unsigned)gy < 32u && (unsigned)gx < 32u)
            v = Y[img * 16384 + c * 1024 + gy * 32 + gx];
        sY[i] = v;
    }
    __syncthreads();

    const int tx = htid & 31, ty = htid >> 5;
    float* sHh = sH + half * YTILE;

    for (int g = 0; g < 8; g++) {
        const int b = b0 + 2 * g + half;
        const float q0 = __ldg(q + b * 4 + 0), q1 = __ldg(q + b * 4 + 1);
        const float q2 = __ldg(q + b * 4 + 2), q3 = __ldg(q + b * 4 + 3);

        // combine + relu (pointwise, same flat layout)
        for (int i = htid; i < YTILE; i += 256) {
            float v = fmaf(q0, sY[i],
                      fmaf(q1, sY[YTILE + i],
                      fmaf(q2, sY[2 * YTILE + i],
                      fmaf(q3, sY[3 * YTILE + i], sY[4 * YTILE + i]))));
            sHh[i] = fmaxf(v, 0.f);
        }
        __syncthreads();

        // dconv2 (16->3) + sigmoid
        ull acc2 = pk2(s_b[0], s_b[1]);
        float acc = s_b[2];
#pragma unroll
        for (int ci = 0; ci < 16; ci++) {
            float v[9];
#pragma unroll
            for (int dy = 0; dy < 3; dy++)
#pragma unroll
                for (int dx = 0; dx < 3; dx++)
                    v[dy * 3 + dx] = sHh[ci * 340 + (ty + dy) * 34 + tx + dx];
#pragma unroll
            for (int k = 0; k < 9; k++) {
                ull vv = pk2(v[k], v[k]);
                acc2 = fma2(vv, c_w.wdp[ci * 9 + k], acc2);
                acc  = fmaf(v[k], c_w.wds[ci * 9 + k], acc);
            }
        }
        float r0, r1;
        upk2(acc2, r0, r1);
        float* outp = out + (size_t)b * 3 * 1024 + (y0 + ty) * 32 + tx;
        outp[0]    = __fdividef(1.f, 1.f + __expf(-r0));
        outp[1024] = __fdividef(1.f, 1.f + __expf(-r1));
        outp[2048] = __fdividef(1.f, 1.f + __expf(-acc));
        __syncthreads();
    }
}

// ---------------------------------------------------------------------------

extern "C" void kernel_launch(void* const* d_in, const int* in_sizes, int n_in,
                              void* d_out, int out_size)
{
    const float* x   = (const float*)d_in[0];
    const float* c1w = (const float*)d_in[1];
    const float* c1b = (const float*)d_in[2];
    const float* c2w = (const float*)d_in[3];
    const float* c2b = (const float*)d_in[4];
    const float* fcw = (const float*)d_in[5];
    const float* fcb = (const float*)d_in[6];
    const float* qw  = (const float*)d_in[7];
    const float* f2w = (const float*)d_in[8];
    const float* f2b = (const float*)d_in[9];
    const float* d1w = (const float*)d_in[10];
    const float* d1b = (const float*)d_in[11];
    const float* d2w = (const float*)d_in[12];
    const float* d2b = (const float*)d_in[13];
    float* out = (float*)d_out;

    float *part, *qv, *Y, *pk;
    float2* V;
    cudaGetSymbolAddress((void**)&part, g_part);
    cudaGetSymbolAddress((void**)&qv,   g_q);
    cudaGetSymbolAddress((void**)&Y,    g_Y);
    cudaGetSymbolAddress((void**)&V,    g_V);
    cudaGetSymbolAddress((void**)&pk,   g_pk);

    static int smem_set = 0;
    if (!smem_set) {
        cudaFuncSetAttribute(fused_out_kernel,
                             cudaFuncAttributeMaxDynamicSharedMemorySize,
                             7 * YTILE * 4);
        smem_set = 1;
    }

    setup_kernel<<<8, 256>>>(c1w, c2w, d1w, d2w, qw, V);
    cudaMemcpyToSymbolAsync(c_w, pk, sizeof(CW), 0, cudaMemcpyDeviceToDevice, 0);

    ybuild_kernel<<<160, 256>>>(f2w, f2b, d1b, Y);
    conv12_kernel<<<dim3(4, BATCH), 320>>>(x, c1b, c2b, fcw, part);
    quantum_kernel<<<BATCH / 128, 128>>>(part, fcb, V, qv);
    fused_out_kernel<<<dim3(4, BATCH / 16), 512, 7 * YTILE * 4>>>(qv, Y, d2b, out);
}